// round 3
// baseline (speedup 1.0000x reference)
#include <cuda_runtime.h>
#include <math_constants.h>

// LinearAttention restructured:
//   k = W_k x                      (GEMM 1, per batch [128,128]x[128,16384])
//   stats: rowwise max/sumexp of k
//   S[d,c] = sum_n exp(k[d,n]-max_d) x[c,n]   (GEMM 2, partials over n-chunks)
//   S' = S * inv_sum ; ctx[h,d,e] = sum_c W_v[h32+e,c] S'[h32+d,c]
//   M_b[o,c] = sum_{h,d,e} W_out[o,h32+e] ctx[h,d,e] W_q[h32+d,c]
//   y = M_b x + b_out              (GEMM 3)
// v and q are never materialized. All heavy GEMMs use packed fma.rn.f32x2.
// kernel_launch contains ONLY kernel launches (no runtime API at all):
// all scratch lives in __device__ globals referenced directly from device code.

#define BATCH 8
#define CD    128
#define NND   16384
#define NCH   32
#define CHN   512

typedef unsigned long long ull;

__device__ float g_k[BATCH * CD * NND];          // 64 MB
__device__ float g_statM[BATCH * CD];
__device__ float g_statS[BATCH * CD];
__device__ float g_Spart[BATCH * NCH * CD * CD]; // 16 MB
__device__ float g_S[BATCH * CD * CD];
__device__ float g_ctx[BATCH * 4 * 32 * 32];
__device__ float g_U[BATCH * CD * CD];
__device__ float g_M[BATCH * CD * CD];

__device__ __forceinline__ ull pk2(float v) {
    ull r;
    asm("mov.b64 %0, {%1, %1};" : "=l"(r) : "r"(__float_as_uint(v)));
    return r;
}
__device__ __forceinline__ void fma2(ull &c, ull a, ull b) {
    asm("fma.rn.f32x2 %0, %1, %2, %0;" : "+l"(c) : "l"(a), "l"(b));
}
__device__ __forceinline__ float2 up2(ull v) {
    unsigned lo, hi;
    asm("mov.b64 {%0, %1}, %2;" : "=r"(lo), "=r"(hi) : "l"(v));
    return make_float2(__uint_as_float(lo), __uint_as_float(hi));
}

// ---------------------------------------------------------------------------
// GEMM: Y[b, r, n] = sum_c W[r,c] X[b,c,n] (+ bias[r])
// FINAL=false: W = parameter (w_k rows of w_qkv), Y = g_k, no bias.
// FINAL=true:  W = g_M (per-batch),               Y = parameter, bias added.
// Block tile: 128 rows x 128 n-cols, K = 128 in 4 chunks of 32.
// 256 threads, 8x8 micro-tile (split 4+4), acc packed as f32x2 pairs.
// ---------------------------------------------------------------------------
template <bool FINAL>
__global__ __launch_bounds__(256, 2) void gemm_fw(
    const float* __restrict__ Wp, const float* __restrict__ X,
    float* __restrict__ Yp, const float* __restrict__ bias)
{
    const int b  = blockIdx.y;
    const int n0 = blockIdx.x * 128;
    const float* W  = FINAL ? (g_M + (size_t)b * CD * CD) : Wp;
    const float* Xb = X + (size_t)b * CD * NND;
    float*       Yb = (FINAL ? Yp : g_k) + (size_t)b * CD * NND;

    __shared__ float sW[32][132];   // [k][row], padded
    __shared__ float sX[32][128];   // [k][n]

    const int t  = threadIdx.x;
    const int tx = t & 15;
    const int ty = t >> 4;

    ull acc[8][4];
#pragma unroll
    for (int i = 0; i < 8; i++)
#pragma unroll
        for (int j = 0; j < 4; j++) acc[i][j] = 0ull;

    for (int kc = 0; kc < 4; kc++) {
        const int k0 = kc * 32;
#pragma unroll
        for (int p = 0; p < 4; p++) {
            int idx = p * 256 + t;            // 1024 float4 of X tile
            int c = idx >> 5, n4 = idx & 31;
            float4 v = *(const float4*)(Xb + (size_t)(k0 + c) * NND + n0 + n4 * 4);
            *(float4*)(&sX[c][n4 * 4]) = v;
        }
#pragma unroll
        for (int p = 0; p < 4; p++) {
            int idx = p * 256 + t;            // 1024 float4-loads of W (transposed store)
            int r = idx >> 3, c4 = idx & 7;
            float4 v = *(const float4*)(W + r * CD + k0 + c4 * 4);
            sW[c4 * 4 + 0][r] = v.x; sW[c4 * 4 + 1][r] = v.y;
            sW[c4 * 4 + 2][r] = v.z; sW[c4 * 4 + 3][r] = v.w;
        }
        __syncthreads();
#pragma unroll
        for (int kk = 0; kk < 32; kk++) {
            float4 a0 = *(const float4*)(&sW[kk][ty * 4]);
            float4 a1 = *(const float4*)(&sW[kk][64 + ty * 4]);
            ulonglong2 bv0 = *(const ulonglong2*)(&sX[kk][tx * 4]);
            ulonglong2 bv1 = *(const ulonglong2*)(&sX[kk][64 + tx * 4]);
            ull aa[8] = {pk2(a0.x), pk2(a0.y), pk2(a0.z), pk2(a0.w),
                         pk2(a1.x), pk2(a1.y), pk2(a1.z), pk2(a1.w)};
            ull bb[4] = {bv0.x, bv0.y, bv1.x, bv1.y};
#pragma unroll
            for (int i = 0; i < 8; i++)
#pragma unroll
                for (int j = 0; j < 4; j++) fma2(acc[i][j], aa[i], bb[j]);
        }
        __syncthreads();
    }

#pragma unroll
    for (int i = 0; i < 8; i++) {
        int r = (i < 4) ? (ty * 4 + i) : (64 + ty * 4 + (i - 4));
        float bz = FINAL ? bias[r] : 0.f;
        float2 c0 = up2(acc[i][0]), c1 = up2(acc[i][1]);
        float2 c2 = up2(acc[i][2]), c3 = up2(acc[i][3]);
        float4 o0 = make_float4(c0.x + bz, c0.y + bz, c1.x + bz, c1.y + bz);
        float4 o1 = make_float4(c2.x + bz, c2.y + bz, c3.x + bz, c3.y + bz);
        *(float4*)(Yb + (size_t)r * NND + n0 + tx * 4)      = o0;
        *(float4*)(Yb + (size_t)r * NND + n0 + 64 + tx * 4) = o1;
    }
}

// ---------------------------------------------------------------------------
// Online softmax stats per k-row: max and sum(exp(v - max)).
// ---------------------------------------------------------------------------
__global__ __launch_bounds__(256) void softmax_stats()
{
    const int r = blockIdx.x;   // 0..127
    const int b = blockIdx.y;
    const float* kp = g_k + (size_t)(b * CD + r) * NND;
    const int t = threadIdx.x;

    float m = -CUDART_INF_F, s = 0.f;
#pragma unroll 4
    for (int i = 0; i < 16; i++) {
        float4 v = *(const float4*)(kp + t * 4 + i * 1024);
        float vv[4] = {v.x, v.y, v.z, v.w};
#pragma unroll
        for (int q = 0; q < 4; q++) {
            float x = vv[q];
            if (x > m) { s = s * __expf(m - x); m = x; }
            s += __expf(x - m);
        }
    }
    __shared__ float sm[256], ss[256];
    sm[t] = m; ss[t] = s;
    __syncthreads();
    for (int off = 128; off > 0; off >>= 1) {
        if (t < off) {
            float m1 = sm[t], s1 = ss[t];
            float m2 = sm[t + off], s2 = ss[t + off];
            float M = fmaxf(m1, m2);
            sm[t] = M;
            ss[t] = s1 * __expf(m1 - M) + s2 * __expf(m2 - M);
        }
        __syncthreads();
    }
    if (t == 0) { g_statM[b * CD + r] = sm[0]; g_statS[b * CD + r] = ss[0]; }
}

// ---------------------------------------------------------------------------
// S partials: Spart[b,ch,d,c] = sum_{n in chunk} exp(k[d,n]-max_d) * x[c,n]
// Both operands transposed into [n][row] smem tiles; same f32x2 micro-kernel.
// ---------------------------------------------------------------------------
__global__ __launch_bounds__(256, 2) void s_partial(const float* __restrict__ X)
{
    const int ch = blockIdx.x;  // 0..31
    const int b  = blockIdx.y;
    const int n0 = ch * CHN;
    const float* Xb = X + (size_t)b * CD * NND;
    const float* Kb = g_k + (size_t)b * CD * NND;

    __shared__ float sA[32][132];   // [n][d] exp(k)
    __shared__ float sB[32][132];   // [n][c] x
    __shared__ float sMax[128];

    const int t  = threadIdx.x;
    const int tx = t & 15;
    const int ty = t >> 4;
    if (t < 128) sMax[t] = g_statM[b * CD + t];
    __syncthreads();

    ull acc[8][4];
#pragma unroll
    for (int i = 0; i < 8; i++)
#pragma unroll
        for (int j = 0; j < 4; j++) acc[i][j] = 0ull;

    for (int st = 0; st < 16; st++) {
        const int ns = n0 + st * 32;
#pragma unroll
        for (int p = 0; p < 4; p++) {
            int idx = p * 256 + t;              // 1024: 128 d x 8 float4
            int d = idx >> 3, n4 = idx & 7;
            float4 v = *(const float4*)(Kb + (size_t)d * NND + ns + n4 * 4);
            float mx = sMax[d];
            sA[n4 * 4 + 0][d] = __expf(v.x - mx);
            sA[n4 * 4 + 1][d] = __expf(v.y - mx);
            sA[n4 * 4 + 2][d] = __expf(v.z - mx);
            sA[n4 * 4 + 3][d] = __expf(v.w - mx);
        }
#pragma unroll
        for (int p = 0; p < 4; p++) {
            int idx = p * 256 + t;
            int c = idx >> 3, n4 = idx & 7;
            float4 v = *(const float4*)(Xb + (size_t)c * NND + ns + n4 * 4);
            sB[n4 * 4 + 0][c] = v.x; sB[n4 * 4 + 1][c] = v.y;
            sB[n4 * 4 + 2][c] = v.z; sB[n4 * 4 + 3][c] = v.w;
        }
        __syncthreads();
#pragma unroll
        for (int kk = 0; kk < 32; kk++) {
            float4 a0 = *(const float4*)(&sA[kk][ty * 4]);
            float4 a1 = *(const float4*)(&sA[kk][64 + ty * 4]);
            ulonglong2 bv0 = *(const ulonglong2*)(&sB[kk][tx * 4]);
            ulonglong2 bv1 = *(const ulonglong2*)(&sB[kk][64 + tx * 4]);
            ull aa[8] = {pk2(a0.x), pk2(a0.y), pk2(a0.z), pk2(a0.w),
                         pk2(a1.x), pk2(a1.y), pk2(a1.z), pk2(a1.w)};
            ull bb[4] = {bv0.x, bv0.y, bv1.x, bv1.y};
#pragma unroll
            for (int i = 0; i < 8; i++)
#pragma unroll
                for (int j = 0; j < 4; j++) fma2(acc[i][j], aa[i], bb[j]);
        }
        __syncthreads();
    }

    float* Sp = g_Spart + (size_t)(b * NCH + ch) * CD * CD;
#pragma unroll
    for (int i = 0; i < 8; i++) {
        int r = (i < 4) ? (ty * 4 + i) : (64 + ty * 4 + (i - 4));
        float2 c0 = up2(acc[i][0]), c1 = up2(acc[i][1]);
        float2 c2 = up2(acc[i][2]), c3 = up2(acc[i][3]);
        float4 o0 = make_float4(c0.x, c0.y, c1.x, c1.y);
        float4 o1 = make_float4(c2.x, c2.y, c3.x, c3.y);
        *(float4*)(Sp + r * CD + tx * 4)      = o0;
        *(float4*)(Sp + r * CD + 64 + tx * 4) = o1;
    }
}

// ---------------------------------------------------------------------------
// Reduce partials over chunks + scale by 1/sumexp.
// ---------------------------------------------------------------------------
__global__ void reduce_scale()
{
    const int bd = blockIdx.x;      // b*128 + d
    const int c  = threadIdx.x;     // 128
    const int b  = bd >> 7, d = bd & 127;
    float s = 0.f;
    const float* p = g_Spart + (size_t)(b * NCH) * CD * CD + (size_t)d * CD + c;
    for (int ch = 0; ch < NCH; ch++) s += p[(size_t)ch * CD * CD];
    g_S[(size_t)bd * CD + c] = s / g_statS[bd];
}

// ---------------------------------------------------------------------------
// ctx[b,h,d,e] = sum_c W_v[h*32+e, c] * S[b, h*32+d, c]
// ---------------------------------------------------------------------------
__global__ __launch_bounds__(1024) void ctx_kernel(const float* __restrict__ w_qkv)
{
    const int b = blockIdx.x, h = blockIdx.y;
    __shared__ float sS[32][133];
    __shared__ float sV[32][133];
    const int t = threadIdx.x;
#pragma unroll
    for (int p = 0; p < 4; p++) {
        int idx = p * 1024 + t;
        int dd = idx >> 7, c = idx & 127;
        sS[dd][c] = g_S[(size_t)(b * CD + h * 32 + dd) * CD + c];
        sV[dd][c] = w_qkv[(256 + h * 32 + dd) * CD + c];
    }
    __syncthreads();
    const int d = t >> 5, e = t & 31;
    float a = 0.f;
#pragma unroll 4
    for (int c = 0; c < CD; c++) a += sS[d][c] * sV[e][c];
    g_ctx[(size_t)(b * 4 + h) * 1024 + d * 32 + e] = a;
}

// ---------------------------------------------------------------------------
// U[b,o,hd] = sum_e W_out[o, (hd&~31)+e] * ctx[b, hd, e]
// ---------------------------------------------------------------------------
__global__ __launch_bounds__(1024) void u_kernel(const float* __restrict__ w_out)
{
    const int b = blockIdx.x;
    __shared__ float sc[128 * 33];
    const int t = threadIdx.x;
#pragma unroll
    for (int p = 0; p < 4; p++) {
        int idx = p * 1024 + t;
        int hd = idx >> 5, e = idx & 31;
        sc[hd * 33 + e] = g_ctx[(size_t)b * 4096 + idx];
    }
    __syncthreads();
#pragma unroll
    for (int i = 0; i < 16; i++) {
        int m = i * 1024 + t;
        int o = m >> 7, hd = m & 127;
        const float* wrow = w_out + o * CD + (hd & ~31);
        const float* crow = sc + hd * 33;
        float a = 0.f;
#pragma unroll
        for (int e = 0; e < 32; e++) a += __ldg(wrow + e) * crow[e];
        g_U[(size_t)b * CD * CD + m] = a;
    }
}

// ---------------------------------------------------------------------------
// M[b,o,c] = sum_hd U[b,o,hd] * W_q[hd, c]
// ---------------------------------------------------------------------------
__global__ __launch_bounds__(256) void m_kernel(const float* __restrict__ w_qkv)
{
    const int b = blockIdx.x, ct = blockIdx.y;   // c tile of 32
    __shared__ float sU[128 * 33];
    __shared__ float sQ[32 * 33];
    const int t  = threadIdx.x;
    const int cl = t & 31, og = t >> 5;

    float a[16];
#pragma unroll
    for (int i = 0; i < 16; i++) a[i] = 0.f;

    for (int kc = 0; kc < 4; kc++) {
        int k0 = kc * 32;
        __syncthreads();
#pragma unroll
        for (int p = 0; p < 16; p++) {
            int idx = p * 256 + t;            // 4096
            int o = idx >> 5, kk = idx & 31;
            sU[o * 33 + kk] = g_U[(size_t)b * CD * CD + o * CD + k0 + kk];
        }
#pragma unroll
        for (int p = 0; p < 4; p++) {
            int idx = p * 256 + t;            // 1024
            int kk = idx >> 5, cc = idx & 31;
            sQ[kk * 33 + cc] = w_qkv[(k0 + kk) * CD + ct * 32 + cc];
        }
        __syncthreads();
#pragma unroll 8
        for (int kk = 0; kk < 32; kk++) {
            float bv = sQ[kk * 33 + cl];
#pragma unroll
            for (int i = 0; i < 16; i++) a[i] += sU[(og * 16 + i) * 33 + kk] * bv;
        }
    }
#pragma unroll
    for (int i = 0; i < 16; i++)
        g_M[(size_t)b * CD * CD + (og * 16 + i) * CD + ct * 32 + cl] = a[i];
}

// ---------------------------------------------------------------------------
// kernel_launch: ONLY kernel launches — no runtime API calls of any kind.
// ---------------------------------------------------------------------------
extern "C" void kernel_launch(void* const* d_in, const int* in_sizes, int n_in,
                              void* d_out, int out_size)
{
    const float* x     = (const float*)d_in[0];
    const float* w_qkv = (const float*)d_in[1];
    const float* w_out = (const float*)d_in[2];
    const float* b_out = (const float*)d_in[3];
    float* y = (float*)d_out;

    dim3 gg(128, BATCH);
    gemm_fw<false><<<gg, 256>>>(w_qkv + 128 * CD, x, nullptr, nullptr); // k = W_k x
    softmax_stats<<<dim3(128, BATCH), 256>>>();
    s_partial<<<dim3(NCH, BATCH), 256>>>(x);
    reduce_scale<<<1024, 128>>>();
    ctx_kernel<<<dim3(BATCH, 4), 1024>>>(w_qkv);
    u_kernel<<<BATCH, 1024>>>(w_out);
    m_kernel<<<dim3(BATCH, 4), 256>>>(w_qkv);
    gemm_fw<true><<<gg, 256>>>(nullptr, x, y, b_out);                   // y = M_b x + b
}

// round 8
// speedup vs baseline: 1.3773x; 1.3773x over previous
#include <cuda_runtime.h>
#include <cuda_bf16.h>
#include <cstdint>

// LinearAttention via mma.sync bf16 (sm_100-safe; no tcgen05 — ptxas targets sm_100):
//   convert_x : X fp32 -> Xhi/Xlo bf16, native [b][c][n] layout only
//   gemm_tc<0>: E = exp(W_k x); A=W_k (fp32, split in-kernel), B=X via ldmatrix.trans
//               epilogue: exp, write Ehi/Elo, fused row-sum partials (no atomics)
//   gemm_tc<1>: Spart[b][ch] = E X^T over 512-wide n-chunks; B=X via non-trans ldmatrix
//   reduce_scale / ctx / u / m : tiny fp32 algebra -> per-batch M[128][128]
//   gemm_tc<2>: y = M_b x + b_out
// 3-way bf16 split (hh+hl+lh) accumulated in fp32 keeps rel_err ~1e-5.
// All SMEM static (40KB), kernel_launch = launches only.
// Resubmission of R7 source: bench failure was broker-side (same error seen on the
// untouched stub in R0); fragment mappings/alignment re-audited, no changes needed.

#define BATCH 8
#define CD    128
#define NND   16384
#define NCH   32

typedef unsigned long long ull;

__device__ __nv_bfloat16 g_Xhi [BATCH * CD * NND];
__device__ __nv_bfloat16 g_Xlo [BATCH * CD * NND];
__device__ __nv_bfloat16 g_Ehi [BATCH * CD * NND];
__device__ __nv_bfloat16 g_Elo [BATCH * CD * NND];
__device__ float g_sumP [BATCH * 128 * 2 * CD];     // [b][ntile][warp-n][r]
__device__ float g_Spart[BATCH * NCH * CD * CD];
__device__ float g_S    [BATCH * CD * CD];
__device__ float g_ctx  [BATCH * 4 * 32 * 32];
__device__ float g_U    [BATCH * CD * CD];
__device__ float g_M    [BATCH * CD * CD];

__device__ __forceinline__ uint32_t sm_u32(const void* p) {
    uint32_t a;
    asm("{ .reg .u64 t; cvta.to.shared.u64 t, %1; cvt.u32.u64 %0, t; }" : "=r"(a) : "l"(p));
    return a;
}

#define LDSM4(r0, r1, r2, r3, a) \
    asm volatile("ldmatrix.sync.aligned.m8n8.x4.shared.b16 {%0,%1,%2,%3}, [%4];" \
                 : "=r"(r0), "=r"(r1), "=r"(r2), "=r"(r3) : "r"(a))
#define LDSM4T(r0, r1, r2, r3, a) \
    asm volatile("ldmatrix.sync.aligned.m8n8.x4.trans.shared.b16 {%0,%1,%2,%3}, [%4];" \
                 : "=r"(r0), "=r"(r1), "=r"(r2), "=r"(r3) : "r"(a))
#define MMA16816(d, av, b0, b1) \
    asm volatile("mma.sync.aligned.m16n8k16.row.col.f32.bf16.bf16.f32 " \
                 "{%0,%1,%2,%3}, {%4,%5,%6,%7}, {%8,%9}, {%0,%1,%2,%3};" \
                 : "+f"((d)[0]), "+f"((d)[1]), "+f"((d)[2]), "+f"((d)[3]) \
                 : "r"((av)[0]), "r"((av)[1]), "r"((av)[2]), "r"((av)[3]), \
                   "r"(b0), "r"(b1))

__device__ __forceinline__ void split2(float f, __nv_bfloat16& h, __nv_bfloat16& l) {
    h = __float2bfloat16(f);
    l = __float2bfloat16(f - __bfloat162float(h));
}

// SMEM pitches (bf16 elems). +8 padding keeps ldmatrix phases conflict-free.
#define PA 40     // [128][40]  (A tiles, and MODE1 B tiles)
#define PB 136    // [32][136]  (trans-B tiles for MODE0/2)

// ---------------------------------------------------------------------------
// convert_x: X fp32 -> bf16 hi/lo, native layout. 4 elems/thread.
// ---------------------------------------------------------------------------
__global__ __launch_bounds__(256) void convert_x(const float* __restrict__ X)
{
    const size_t idx = ((size_t)blockIdx.x * 256 + threadIdx.x) * 4;
    float4 v = *(const float4*)(X + idx);
    float f[4] = {v.x, v.y, v.z, v.w};
    ull vh = 0, vl = 0;
#pragma unroll
    for (int j = 0; j < 4; j++) {
        __nv_bfloat16 h, l; split2(f[j], h, l);
        vh |= (ull)__bfloat16_as_ushort(h) << (16 * j);
        vl |= (ull)__bfloat16_as_ushort(l) << (16 * j);
    }
    *(ull*)(g_Xhi + idx) = vh;
    *(ull*)(g_Xlo + idx) = vl;
}

// ---------------------------------------------------------------------------
// gemm_tc<MODE>: 128x128 output tile, 8 warps (4m x 2n), warp tile 32x64.
//  MODE 0: E = exp(W_k X)  A fp32 W (split in-kernel), B = X (ldmatrix.trans)
//  MODE 1: Spart = E X^T   A = Ehi/lo bf16, B = X (non-trans), K=512 chunk
//  MODE 2: y = M_b X + b   A fp32 g_M, B = X (trans)
// ---------------------------------------------------------------------------
template <int MODE>
__global__ __launch_bounds__(256) void gemm_tc(
    const float* __restrict__ Afp, const float* __restrict__ bias,
    float* __restrict__ Y)
{
    constexpr bool BT = (MODE != 1);
    constexpr int KSTAGES = (MODE == 1) ? 16 : 4;

    __shared__ __nv_bfloat16 sAh[128 * PA], sAl[128 * PA];
    __shared__ __nv_bfloat16 sBh[5120],     sBl[5120];   // BT: 32*PB=4352; else 128*PA=5120

    const int t = threadIdx.x, wid = t >> 5, L = t & 31;
    const int b = blockIdx.y, nt = blockIdx.x;
    const int n0 = (MODE == 1) ? 0 : nt * 128;           // output col origin
    const int wm = wid & 3, wn = wid >> 2;
    const int m0w = wm * 32, n0w = wn * 64;

    float acc[2][8][4];
#pragma unroll
    for (int i = 0; i < 2; i++)
#pragma unroll
        for (int j = 0; j < 8; j++)
#pragma unroll
            for (int q = 0; q < 4; q++) acc[i][j][q] = 0.f;

    const uint32_t uAh = sm_u32(sAh), uAl = sm_u32(sAl);
    const uint32_t uBh = sm_u32(sBh), uBl = sm_u32(sBl);

    for (int st = 0; st < KSTAGES; st++) {
        // ---- stage A ----
        if (MODE == 1) {
            const int ks = nt * 512 + st * 32;
            const __nv_bfloat16* Ah = g_Ehi + (size_t)b * CD * NND + ks;
            const __nv_bfloat16* Al = g_Elo + (size_t)b * CD * NND + ks;
            const int cc = (t & 3) * 8;
#pragma unroll
            for (int h = 0; h < 2; h++) {
                int row = (t >> 2) + h * 64;
                *(uint4*)&sAh[row * PA + cc] = *(const uint4*)(Ah + (size_t)row * NND + cc);
                *(uint4*)&sAl[row * PA + cc] = *(const uint4*)(Al + (size_t)row * NND + cc);
            }
        } else {
            const int k0 = st * 32;
            const float* A = (MODE == 0) ? Afp : (g_M + (size_t)b * CD * CD);
            const int row = t >> 1, cbase = (t & 1) * 16;
#pragma unroll
            for (int i = 0; i < 4; i++) {
                int col = cbase + i * 4;
                float4 v = *(const float4*)(A + row * CD + k0 + col);
                float f[4] = {v.x, v.y, v.z, v.w};
                ull vh = 0, vl = 0;
#pragma unroll
                for (int j = 0; j < 4; j++) {
                    __nv_bfloat16 h, l; split2(f[j], h, l);
                    vh |= (ull)__bfloat16_as_ushort(h) << (16 * j);
                    vl |= (ull)__bfloat16_as_ushort(l) << (16 * j);
                }
                *(ull*)&sAh[row * PA + col] = vh;
                *(ull*)&sAl[row * PA + col] = vl;
            }
        }
        // ---- stage B ----
        if (BT) {   // [k=c rows 32][n cols 128] from X[c][n]
            const int k0 = st * 32;
            const __nv_bfloat16* Bh = g_Xhi + ((size_t)b * CD + k0) * NND + n0;
            const __nv_bfloat16* Bl = g_Xlo + ((size_t)b * CD + k0) * NND + n0;
#pragma unroll
            for (int h = 0; h < 2; h++) {
                int idx = h * 256 + t;
                int row = idx >> 4, cc = (idx & 15) * 8;
                *(uint4*)&sBh[row * PB + cc] = *(const uint4*)(Bh + (size_t)row * NND + cc);
                *(uint4*)&sBl[row * PB + cc] = *(const uint4*)(Bl + (size_t)row * NND + cc);
            }
        } else {    // [c rows 128][k=n cols 32] from X[c][n]
            const int ks = nt * 512 + st * 32;
            const __nv_bfloat16* Bh = g_Xhi + (size_t)b * CD * NND + ks;
            const __nv_bfloat16* Bl = g_Xlo + (size_t)b * CD * NND + ks;
            const int cc = (t & 3) * 8;
#pragma unroll
            for (int h = 0; h < 2; h++) {
                int row = (t >> 2) + h * 64;
                *(uint4*)&sBh[row * PA + cc] = *(const uint4*)(Bh + (size_t)row * NND + cc);
                *(uint4*)&sBl[row * PA + cc] = *(const uint4*)(Bl + (size_t)row * NND + cc);
            }
        }
        __syncthreads();

        // ---- compute: 2 k16 steps ----
#pragma unroll
        for (int kk = 0; kk < 32; kk += 16) {
            uint32_t ah[2][4], al[2][4];
#pragma unroll
            for (int i = 0; i < 2; i++) {
                uint32_t off = (uint32_t)(((m0w + i * 16 + (L & 15)) * PA
                                + kk + ((L >> 4) << 3)) * 2);
                LDSM4(ah[i][0], ah[i][1], ah[i][2], ah[i][3], uAh + off);
                LDSM4(al[i][0], al[i][1], al[i][2], al[i][3], uAl + off);
            }
            uint32_t bh[8][2], bl[8][2];
#pragma unroll
            for (int j2 = 0; j2 < 4; j2++) {
                uint32_t r0, r1, r2, r3;
                if (BT) {
                    uint32_t off = (uint32_t)(((kk + (L & 15)) * PB
                                    + n0w + j2 * 16 + ((L >> 4) << 3)) * 2);
                    LDSM4T(r0, r1, r2, r3, uBh + off);
                    bh[2*j2][0] = r0; bh[2*j2][1] = r1; bh[2*j2+1][0] = r2; bh[2*j2+1][1] = r3;
                    LDSM4T(r0, r1, r2, r3, uBl + off);
                    bl[2*j2][0] = r0; bl[2*j2][1] = r1; bl[2*j2+1][0] = r2; bl[2*j2+1][1] = r3;
                } else {
                    uint32_t off = (uint32_t)(((n0w + j2 * 16 + (L & 15)) * PA
                                    + kk + ((L >> 4) << 3)) * 2);
                    LDSM4(r0, r1, r2, r3, uBh + off);
                    bh[2*j2][0] = r0; bh[2*j2][1] = r2; bh[2*j2+1][0] = r1; bh[2*j2+1][1] = r3;
                    LDSM4(r0, r1, r2, r3, uBl + off);
                    bl[2*j2][0] = r0; bl[2*j2][1] = r2; bl[2*j2+1][0] = r1; bl[2*j2+1][1] = r3;
                }
            }
#pragma unroll
            for (int i = 0; i < 2; i++)
#pragma unroll
                for (int j = 0; j < 8; j++) {
                    MMA16816(acc[i][j], ah[i], bh[j][0], bh[j][1]);
                    MMA16816(acc[i][j], ah[i], bl[j][0], bl[j][1]);
                    MMA16816(acc[i][j], al[i], bh[j][0], bh[j][1]);
                }
        }
        __syncthreads();
    }

    // ---- epilogue ----
    const int r4 = L >> 2, c2 = (L & 3) * 2;
    if (MODE == 0) {
        float rsum[2][2] = {{0.f, 0.f}, {0.f, 0.f}};
#pragma unroll
        for (int i = 0; i < 2; i++) {
            const int rA = m0w + i * 16 + r4;
#pragma unroll
            for (int j = 0; j < 8; j++) {
                const int col = n0 + n0w + j * 8 + c2;
                float e0 = __expf(acc[i][j][0]), e1 = __expf(acc[i][j][1]);
                float e2 = __expf(acc[i][j][2]), e3 = __expf(acc[i][j][3]);
                rsum[i][0] += e0 + e1; rsum[i][1] += e2 + e3;
                __nv_bfloat16 h, l; ushort2 ph, pl;
                split2(e0, h, l); ph.x = __bfloat16_as_ushort(h); pl.x = __bfloat16_as_ushort(l);
                split2(e1, h, l); ph.y = __bfloat16_as_ushort(h); pl.y = __bfloat16_as_ushort(l);
                *(ushort2*)(g_Ehi + ((size_t)(b * CD + rA)) * NND + col) = ph;
                *(ushort2*)(g_Elo + ((size_t)(b * CD + rA)) * NND + col) = pl;
                split2(e2, h, l); ph.x = __bfloat16_as_ushort(h); pl.x = __bfloat16_as_ushort(l);
                split2(e3, h, l); ph.y = __bfloat16_as_ushort(h); pl.y = __bfloat16_as_ushort(l);
                *(ushort2*)(g_Ehi + ((size_t)(b * CD + rA + 8)) * NND + col) = ph;
                *(ushort2*)(g_Elo + ((size_t)(b * CD + rA + 8)) * NND + col) = pl;
            }
        }
#pragma unroll
        for (int i = 0; i < 2; i++)
#pragma unroll
            for (int hh = 0; hh < 2; hh++) {
                float s = rsum[i][hh];
                s += __shfl_xor_sync(0xFFFFFFFF, s, 1);
                s += __shfl_xor_sync(0xFFFFFFFF, s, 2);
                rsum[i][hh] = s;
            }
        if ((L & 3) == 0) {
            float* sp = g_sumP + (((size_t)b * 128 + nt) * 2 + wn) * CD;
            sp[m0w + r4]      = rsum[0][0];
            sp[m0w + r4 + 8]  = rsum[0][1];
            sp[m0w + r4 + 16] = rsum[1][0];
            sp[m0w + r4 + 24] = rsum[1][1];
        }
    } else if (MODE == 1) {
        float* sp = g_Spart + ((size_t)(b * NCH + nt)) * CD * CD;
#pragma unroll
        for (int i = 0; i < 2; i++) {
            const int rA = m0w + i * 16 + r4;
#pragma unroll
            for (int j = 0; j < 8; j++) {
                const int col = n0w + j * 8 + c2;
                *(float2*)(sp + rA * CD + col)       = make_float2(acc[i][j][0], acc[i][j][1]);
                *(float2*)(sp + (rA + 8) * CD + col) = make_float2(acc[i][j][2], acc[i][j][3]);
            }
        }
    } else {
#pragma unroll
        for (int i = 0; i < 2; i++) {
            const int rA = m0w + i * 16 + r4;
            const float b1 = bias[rA], b2 = bias[rA + 8];
#pragma unroll
            for (int j = 0; j < 8; j++) {
                const int col = n0 + n0w + j * 8 + c2;
                *(float2*)(Y + ((size_t)(b * CD + rA)) * NND + col) =
                    make_float2(acc[i][j][0] + b1, acc[i][j][1] + b1);
                *(float2*)(Y + ((size_t)(b * CD + rA + 8)) * NND + col) =
                    make_float2(acc[i][j][2] + b2, acc[i][j][3] + b2);
            }
        }
    }
}

// ---------------------------------------------------------------------------
// reduce_scale: S[b][d][c] = (sum_ch Spart) / (sum over 256 sumP entries)
// ---------------------------------------------------------------------------
__global__ void reduce_scale()
{
    const int bd = blockIdx.x;      // b*128 + d
    const int c  = threadIdx.x;     // 128
    const int b  = bd >> 7, d = bd & 127;

    __shared__ float red[128];
    const float* sp = g_sumP + (size_t)b * 128 * 2 * CD;
    red[c] = sp[(c * 2 + 0) * CD + d] + sp[(c * 2 + 1) * CD + d];
    __syncthreads();
    for (int off = 64; off > 0; off >>= 1) {
        if (c < off) red[c] += red[c + off];
        __syncthreads();
    }
    const float inv = 1.0f / red[0];

    float s = 0.f;
    const float* p = g_Spart + (size_t)(b * NCH) * CD * CD + (size_t)d * CD + c;
    for (int ch = 0; ch < NCH; ch++) s += p[(size_t)ch * CD * CD];
    g_S[(size_t)bd * CD + c] = s * inv;
}

__global__ __launch_bounds__(1024) void ctx_kernel(const float* __restrict__ w_qkv)
{
    const int b = blockIdx.x, h = blockIdx.y;
    __shared__ float sS[32][133];
    __shared__ float sV[32][133];
    const int t = threadIdx.x;
#pragma unroll
    for (int p = 0; p < 4; p++) {
        int idx = p * 1024 + t;
        int dd = idx >> 7, c = idx & 127;
        sS[dd][c] = g_S[(size_t)(b * CD + h * 32 + dd) * CD + c];
        sV[dd][c] = w_qkv[(256 + h * 32 + dd) * CD + c];
    }
    __syncthreads();
    const int d = t >> 5, e = t & 31;
    float a = 0.f;
#pragma unroll 4
    for (int c = 0; c < CD; c++) a += sS[d][c] * sV[e][c];
    g_ctx[(size_t)(b * 4 + h) * 1024 + d * 32 + e] = a;
}

__global__ __launch_bounds__(1024) void u_kernel(const float* __restrict__ w_out)
{
    const int b = blockIdx.x;
    __shared__ float sc[128 * 33];
    const int t = threadIdx.x;
#pragma unroll
    for (int p = 0; p < 4; p++) {
        int idx = p * 1024 + t;
        sc[(idx >> 5) * 33 + (idx & 31)] = g_ctx[(size_t)b * 4096 + idx];
    }
    __syncthreads();
#pragma unroll
    for (int i = 0; i < 16; i++) {
        int m = i * 1024 + t;
        int o = m >> 7, hd = m & 127;
        const float* wrow = w_out + o * CD + (hd & ~31);
        const float* crow = sc + hd * 33;
        float a = 0.f;
#pragma unroll
        for (int e = 0; e < 32; e++) a += __ldg(wrow + e) * crow[e];
        g_U[(size_t)b * CD * CD + m] = a;
    }
}

__global__ __launch_bounds__(256) void m_kernel(const float* __restrict__ w_qkv)
{
    const int b = blockIdx.x, ct = blockIdx.y;
    __shared__ float sU[128 * 33];
    __shared__ float sQ[32 * 33];
    const int t  = threadIdx.x;
    const int cl = t & 31, og = t >> 5;

    float a[16];
#pragma unroll
    for (int i = 0; i < 16; i++) a[i] = 0.f;

    for (int kc = 0; kc < 4; kc++) {
        int k0 = kc * 32;
        __syncthreads();
#pragma unroll
        for (int p = 0; p < 16; p++) {
            int idx = p * 256 + t;
            sU[(idx >> 5) * 33 + (idx & 31)] =
                g_U[(size_t)b * CD * CD + (idx >> 5) * CD + k0 + (idx & 31)];
        }
#pragma unroll
        for (int p = 0; p < 4; p++) {
            int idx = p * 256 + t;
            sQ[(idx >> 5) * 33 + (idx & 31)] =
                w_qkv[(k0 + (idx >> 5)) * CD + ct * 32 + (idx & 31)];
        }
        __syncthreads();
#pragma unroll 8
        for (int kk = 0; kk < 32; kk++) {
            float bv = sQ[kk * 33 + cl];
#pragma unroll
            for (int i = 0; i < 16; i++) a[i] += sU[(og * 16 + i) * 33 + kk] * bv;
        }
    }
#pragma unroll
    for (int i = 0; i < 16; i++)
        g_M[(size_t)b * CD * CD + (og * 16 + i) * CD + ct * 32 + cl] = a[i];
}

// ---------------------------------------------------------------------------
// kernel_launch: launches only. No attributes needed (all static smem <= 48KB).
// ---------------------------------------------------------------------------
extern "C" void kernel_launch(void* const* d_in, const int* in_sizes, int n_in,
                              void* d_out, int out_size)
{
    const float* x     = (const float*)d_in[0];
    const float* w_qkv = (const float*)d_in[1];
    const float* w_out = (const float*)d_in[2];
    const float* b_out = (const float*)d_in[3];
    float* y = (float*)d_out;

    convert_x<<<BATCH * CD * NND / 1024, 256>>>(x);
    gemm_tc<0><<<dim3(128, BATCH), 256>>>(w_qkv + 128 * CD, nullptr, nullptr);
    gemm_tc<1><<<dim3(NCH, BATCH), 256>>>(nullptr, nullptr, nullptr);
    reduce_scale<<<1024, 128>>>();
    ctx_kernel<<<dim3(BATCH, 4), 1024>>>(w_qkv);
    u_kernel<<<BATCH, 1024>>>(w_out);
    m_kernel<<<dim3(BATCH, 4), 256>>>(w_qkv);
    gemm_tc<2><<<dim3(128, BATCH), 256>>>(nullptr, b_out, y);
}

// round 9
// speedup vs baseline: 1.4535x; 1.0553x over previous
#include <cuda_runtime.h>
#include <cuda_bf16.h>
#include <cstdint>

// LinearAttention via mma.sync bf16 (sm_100-safe target):
//   gemm_tc<0>: E = exp(W_k x)  (A = W_k fp32, B = X fp32 trans-staged; E stored fp32)
//               epilogue: exp, fused row-sum partials
//   gemm_tc<1>: Spart[b][ch] = E X^T  (A = E fp32, B = X fp32, both split at staging)
//   reduce_scale / ctx / u / m : tiny fp32 algebra -> per-batch M[128][128]
//   gemm_tc<2>: y = M_b x + b_out
// Every operand is fp32 in GMEM and bf16 hi/lo-split ONLY at SMEM staging time:
// no conversion pass, no bf16 copies of X or E (halves global traffic vs R8).
// 3-way split (hh+hl+lh) accumulated in fp32: rel_err ~5e-6.
// All SMEM static (~41KB), kernel_launch = launches only.

#define BATCH 8
#define CD    128
#define NND   16384
#define NCH   32

typedef unsigned long long ull;

__device__ float g_E    [BATCH * CD * NND];          // exp(k), fp32, 64MB
__device__ float g_sumP [BATCH * 128 * 2 * CD];      // [b][ntile][warp-n][r]
__device__ float g_Spart[BATCH * NCH * CD * CD];
__device__ float g_S    [BATCH * CD * CD];
__device__ float g_ctx  [BATCH * 4 * 32 * 32];
__device__ float g_U    [BATCH * CD * CD];
__device__ float g_M    [BATCH * CD * CD];

__device__ __forceinline__ uint32_t sm_u32(const void* p) {
    uint32_t a;
    asm("{ .reg .u64 t; cvta.to.shared.u64 t, %1; cvt.u32.u64 %0, t; }" : "=r"(a) : "l"(p));
    return a;
}

#define LDSM4(r0, r1, r2, r3, a) \
    asm volatile("ldmatrix.sync.aligned.m8n8.x4.shared.b16 {%0,%1,%2,%3}, [%4];" \
                 : "=r"(r0), "=r"(r1), "=r"(r2), "=r"(r3) : "r"(a))
#define LDSM4T(r0, r1, r2, r3, a) \
    asm volatile("ldmatrix.sync.aligned.m8n8.x4.trans.shared.b16 {%0,%1,%2,%3}, [%4];" \
                 : "=r"(r0), "=r"(r1), "=r"(r2), "=r"(r3) : "r"(a))
#define MMA16816(d, av, b0, b1) \
    asm volatile("mma.sync.aligned.m16n8k16.row.col.f32.bf16.bf16.f32 " \
                 "{%0,%1,%2,%3}, {%4,%5,%6,%7}, {%8,%9}, {%0,%1,%2,%3};" \
                 : "+f"((d)[0]), "+f"((d)[1]), "+f"((d)[2]), "+f"((d)[3]) \
                 : "r"((av)[0]), "r"((av)[1]), "r"((av)[2]), "r"((av)[3]), \
                   "r"(b0), "r"(b1))

__device__ __forceinline__ void split2(float f, __nv_bfloat16& h, __nv_bfloat16& l) {
    h = __float2bfloat16(f);
    l = __float2bfloat16(f - __bfloat162float(h));
}

// Pack a float4 into hi/lo bf16x4 words.
__device__ __forceinline__ void split4(float4 v, ull& vh, ull& vl) {
    float f[4] = {v.x, v.y, v.z, v.w};
    vh = 0; vl = 0;
#pragma unroll
    for (int j = 0; j < 4; j++) {
        __nv_bfloat16 h, l; split2(f[j], h, l);
        vh |= (ull)__bfloat16_as_ushort(h) << (16 * j);
        vl |= (ull)__bfloat16_as_ushort(l) << (16 * j);
    }
}

// SMEM pitches (bf16 elems). +8 padding keeps ldmatrix phases conflict-free.
#define PA 40     // [128][40]  (A tiles, and MODE1 B tiles)
#define PB 136    // [32][136]  (trans-B tiles for MODE0/2)

// ---------------------------------------------------------------------------
// gemm_tc<MODE>: 128x128 output tile, 8 warps (4m x 2n), warp tile 32x64.
// All GMEM operands fp32, split to bf16 hi/lo at SMEM staging.
//  MODE 0: E = exp(W_k X)   A = W_k [r][c] pitch CD,  B = X (trans), E fp32 out
//  MODE 1: Spart = E X^T    A = E  [d][n] pitch NND,  B = X (non-trans), K=512 chunk
//  MODE 2: y = M_b X + b    A = g_M [o][c] pitch CD,  B = X (trans)
// ---------------------------------------------------------------------------
template <int MODE>
__global__ __launch_bounds__(256) void gemm_tc(
    const float* __restrict__ Afp, const float* __restrict__ X,
    const float* __restrict__ bias, float* __restrict__ Y)
{
    constexpr bool BT = (MODE != 1);
    constexpr int KSTAGES = (MODE == 1) ? 16 : 4;

    __shared__ __nv_bfloat16 sAh[128 * PA], sAl[128 * PA];
    __shared__ __nv_bfloat16 sBh[5120],     sBl[5120];   // BT: 32*PB=4352; else 128*PA=5120

    const int t = threadIdx.x, wid = t >> 5, L = t & 31;
    const int b = blockIdx.y, nt = blockIdx.x;
    const int n0 = (MODE == 1) ? 0 : nt * 128;           // output col origin
    const int wm = wid & 3, wn = wid >> 2;
    const int m0w = wm * 32, n0w = wn * 64;

    float acc[2][8][4];
#pragma unroll
    for (int i = 0; i < 2; i++)
#pragma unroll
        for (int j = 0; j < 8; j++)
#pragma unroll
            for (int q = 0; q < 4; q++) acc[i][j][q] = 0.f;

    const uint32_t uAh = sm_u32(sAh), uAl = sm_u32(sAl);
    const uint32_t uBh = sm_u32(sBh), uBl = sm_u32(sBl);

    for (int st = 0; st < KSTAGES; st++) {
        // ---- stage A: fp32 [128 rows][32 k-cols], split -> sAh/sAl (PA pitch) ----
        {
            const float* A; size_t apitch; int ak0;
            if (MODE == 1) {
                A = g_E + (size_t)b * CD * NND;           // rows d, cols n
                apitch = NND; ak0 = nt * 512 + st * 32;
            } else {
                A = (MODE == 0) ? Afp : (g_M + (size_t)b * CD * CD);
                apitch = CD; ak0 = st * 32;
            }
            const int row = t >> 1, cbase = (t & 1) * 16;
#pragma unroll
            for (int i = 0; i < 4; i++) {
                int col = cbase + i * 4;
                float4 v = *(const float4*)(A + (size_t)row * apitch + ak0 + col);
                ull vh, vl; split4(v, vh, vl);
                *(ull*)&sAh[row * PA + col] = vh;
                *(ull*)&sAl[row * PA + col] = vl;
            }
        }
        // ---- stage B: fp32 X, split -> sBh/sBl ----
        if (BT) {   // [k=c rows 32][n cols 128] from X[c][n], trans layout (PB pitch)
            const int k0 = st * 32;
            const float* B = X + ((size_t)b * CD + k0) * NND + n0;
            const int row = t >> 3, cb = (t & 7) * 16;
#pragma unroll
            for (int i = 0; i < 4; i++) {
                int col = cb + i * 4;
                float4 v = *(const float4*)(B + (size_t)row * NND + col);
                ull vh, vl; split4(v, vh, vl);
                *(ull*)&sBh[row * PB + col] = vh;
                *(ull*)&sBl[row * PB + col] = vl;
            }
        } else {    // [c rows 128][k=n cols 32] from X[c][n], PA pitch
            const int ks = nt * 512 + st * 32;
            const float* B = X + (size_t)b * CD * NND + ks;
            const int row = t >> 1, cbase = (t & 1) * 16;
#pragma unroll
            for (int i = 0; i < 4; i++) {
                int col = cbase + i * 4;
                float4 v = *(const float4*)(B + (size_t)row * NND + col);
                ull vh, vl; split4(v, vh, vl);
                *(ull*)&sBh[row * PA + col] = vh;
                *(ull*)&sBl[row * PA + col] = vl;
            }
        }
        __syncthreads();

        // ---- compute: 2 k16 steps ----
#pragma unroll
        for (int kk = 0; kk < 32; kk += 16) {
            uint32_t ah[2][4], al[2][4];
#pragma unroll
            for (int i = 0; i < 2; i++) {
                uint32_t off = (uint32_t)(((m0w + i * 16 + (L & 15)) * PA
                                + kk + ((L >> 4) << 3)) * 2);
                LDSM4(ah[i][0], ah[i][1], ah[i][2], ah[i][3], uAh + off);
                LDSM4(al[i][0], al[i][1], al[i][2], al[i][3], uAl + off);
            }
            uint32_t bh[8][2], bl[8][2];
#pragma unroll
            for (int j2 = 0; j2 < 4; j2++) {
                uint32_t r0, r1, r2, r3;
                if (BT) {
                    uint32_t off = (uint32_t)(((kk + (L & 15)) * PB
                                    + n0w + j2 * 16 + ((L >> 4) << 3)) * 2);
                    LDSM4T(r0, r1, r2, r3, uBh + off);
                    bh[2*j2][0] = r0; bh[2*j2][1] = r1; bh[2*j2+1][0] = r2; bh[2*j2+1][1] = r3;
                    LDSM4T(r0, r1, r2, r3, uBl + off);
                    bl[2*j2][0] = r0; bl[2*j2][1] = r1; bl[2*j2+1][0] = r2; bl[2*j2+1][1] = r3;
                } else {
                    uint32_t off = (uint32_t)(((n0w + j2 * 16 + (L & 15)) * PA
                                    + kk + ((L >> 4) << 3)) * 2);
                    LDSM4(r0, r1, r2, r3, uBh + off);
                    bh[2*j2][0] = r0; bh[2*j2][1] = r2; bh[2*j2+1][0] = r1; bh[2*j2+1][1] = r3;
                    LDSM4(r0, r1, r2, r3, uBl + off);
                    bl[2*j2][0] = r0; bl[2*j2][1] = r2; bl[2*j2+1][0] = r1; bl[2*j2+1][1] = r3;
                }
            }
#pragma unroll
            for (int i = 0; i < 2; i++)
#pragma unroll
                for (int j = 0; j < 8; j++) {
                    MMA16816(acc[i][j], ah[i], bh[j][0], bh[j][1]);
                    MMA16816(acc[i][j], ah[i], bl[j][0], bl[j][1]);
                    MMA16816(acc[i][j], al[i], bh[j][0], bh[j][1]);
                }
        }
        __syncthreads();
    }

    // ---- epilogue ----
    const int r4 = L >> 2, c2 = (L & 3) * 2;
    if (MODE == 0) {
        float rsum[2][2] = {{0.f, 0.f}, {0.f, 0.f}};
#pragma unroll
        for (int i = 0; i < 2; i++) {
            const int rA = m0w + i * 16 + r4;
#pragma unroll
            for (int j = 0; j < 8; j++) {
                const int col = n0 + n0w + j * 8 + c2;
                float e0 = __expf(acc[i][j][0]), e1 = __expf(acc[i][j][1]);
                float e2 = __expf(acc[i][j][2]), e3 = __expf(acc[i][j][3]);
                rsum[i][0] += e0 + e1; rsum[i][1] += e2 + e3;
                *(float2*)(g_E + ((size_t)(b * CD + rA)) * NND + col)     = make_float2(e0, e1);
                *(float2*)(g_E + ((size_t)(b * CD + rA + 8)) * NND + col) = make_float2(e2, e3);
            }
        }
#pragma unroll
        for (int i = 0; i < 2; i++)
#pragma unroll
            for (int hh = 0; hh < 2; hh++) {
                float s = rsum[i][hh];
                s += __shfl_xor_sync(0xFFFFFFFF, s, 1);
                s += __shfl_xor_sync(0xFFFFFFFF, s, 2);
                rsum[i][hh] = s;
            }
        if ((L & 3) == 0) {
            float* sp = g_sumP + (((size_t)b * 128 + nt) * 2 + wn) * CD;
            sp[m0w + r4]      = rsum[0][0];
            sp[m0w + r4 + 8]  = rsum[0][1];
            sp[m0w + r4 + 16] = rsum[1][0];
            sp[m0w + r4 + 24] = rsum[1][1];
        }
    } else if (MODE == 1) {
        float* sp = g_Spart + ((size_t)(b * NCH + nt)) * CD * CD;
#pragma unroll
        for (int i = 0; i < 2; i++) {
            const int rA = m0w + i * 16 + r4;
#pragma unroll
            for (int j = 0; j < 8; j++) {
                const int col = n0w + j * 8 + c2;
                *(float2*)(sp + rA * CD + col)       = make_float2(acc[i][j][0], acc[i][j][1]);
                *(float2*)(sp + (rA + 8) * CD + col) = make_float2(acc[i][j][2], acc[i][j][3]);
            }
        }
    } else {
#pragma unroll
        for (int i = 0; i < 2; i++) {
            const int rA = m0w + i * 16 + r4;
            const float b1 = bias[rA], b2 = bias[rA + 8];
#pragma unroll
            for (int j = 0; j < 8; j++) {
                const int col = n0 + n0w + j * 8 + c2;
                *(float2*)(Y + ((size_t)(b * CD + rA)) * NND + col) =
                    make_float2(acc[i][j][0] + b1, acc[i][j][1] + b1);
                *(float2*)(Y + ((size_t)(b * CD + rA + 8)) * NND + col) =
                    make_float2(acc[i][j][2] + b2, acc[i][j][3] + b2);
            }
        }
    }
}

// ---------------------------------------------------------------------------
// reduce_scale: S[b][d][c] = (sum_ch Spart) / (sum over 256 sumP entries)
// ---------------------------------------------------------------------------
__global__ void reduce_scale()
{
    const int bd = blockIdx.x;      // b*128 + d
    const int c  = threadIdx.x;     // 128
    const int b  = bd >> 7, d = bd & 127;

    __shared__ float red[128];
    const float* sp = g_sumP + (size_t)b * 128 * 2 * CD;
    red[c] = sp[(c * 2 + 0) * CD + d] + sp[(c * 2 + 1) * CD + d];
    __syncthreads();
    for (int off = 64; off > 0; off >>= 1) {
        if (c < off) red[c] += red[c + off];
        __syncthreads();
    }
    const float inv = 1.0f / red[0];

    float s = 0.f;
    const float* p = g_Spart + (size_t)(b * NCH) * CD * CD + (size_t)d * CD + c;
    for (int ch = 0; ch < NCH; ch++) s += p[(size_t)ch * CD * CD];
    g_S[(size_t)bd * CD + c] = s * inv;
}

__global__ __launch_bounds__(1024) void ctx_kernel(const float* __restrict__ w_qkv)
{
    const int b = blockIdx.x, h = blockIdx.y;
    __shared__ float sS[32][133];
    __shared__ float sV[32][133];
    const int t = threadIdx.x;
#pragma unroll
    for (int p = 0; p < 4; p++) {
        int idx = p * 1024 + t;
        int dd = idx >> 7, c = idx & 127;
        sS[dd][c] = g_S[(size_t)(b * CD + h * 32 + dd) * CD + c];
        sV[dd][c] = w_qkv[(256 + h * 32 + dd) * CD + c];
    }
    __syncthreads();
    const int d = t >> 5, e = t & 31;
    float a = 0.f;
#pragma unroll 4
    for (int c = 0; c < CD; c++) a += sS[d][c] * sV[e][c];
    g_ctx[(size_t)(b * 4 + h) * 1024 + d * 32 + e] = a;
}

__global__ __launch_bounds__(1024) void u_kernel(const float* __restrict__ w_out)
{
    const int b = blockIdx.x;
    __shared__ float sc[128 * 33];
    const int t = threadIdx.x;
#pragma unroll
    for (int p = 0; p < 4; p++) {
        int idx = p * 1024 + t;
        sc[(idx >> 5) * 33 + (idx & 31)] = g_ctx[(size_t)b * 4096 + idx];
    }
    __syncthreads();
#pragma unroll
    for (int i = 0; i < 16; i++) {
        int m = i * 1024 + t;
        int o = m >> 7, hd = m & 127;
        const float* wrow = w_out + o * CD + (hd & ~31);
        const float* crow = sc + hd * 33;
        float a = 0.f;
#pragma unroll
        for (int e = 0; e < 32; e++) a += __ldg(wrow + e) * crow[e];
        g_U[(size_t)b * CD * CD + m] = a;
    }
}

__global__ __launch_bounds__(256) void m_kernel(const float* __restrict__ w_qkv)
{
    const int b = blockIdx.x, ct = blockIdx.y;
    __shared__ float sU[128 * 33];
    __shared__ float sQ[32 * 33];
    const int t  = threadIdx.x;
    const int cl = t & 31, og = t >> 5;

    float a[16];
#pragma unroll
    for (int i = 0; i < 16; i++) a[i] = 0.f;

    for (int kc = 0; kc < 4; kc++) {
        int k0 = kc * 32;
        __syncthreads();
#pragma unroll
        for (int p = 0; p < 16; p++) {
            int idx = p * 256 + t;
            sU[(idx >> 5) * 33 + (idx & 31)] =
                g_U[(size_t)b * CD * CD + (idx >> 5) * CD + k0 + (idx & 31)];
        }
#pragma unroll
        for (int p = 0; p < 4; p++) {
            int idx = p * 256 + t;
            sQ[(idx >> 5) * 33 + (idx & 31)] =
                w_qkv[(k0 + (idx >> 5)) * CD + ct * 32 + (idx & 31)];
        }
        __syncthreads();
#pragma unroll 8
        for (int kk = 0; kk < 32; kk++) {
            float bv = sQ[kk * 33 + cl];
#pragma unroll
            for (int i = 0; i < 16; i++) a[i] += sU[(og * 16 + i) * 33 + kk] * bv;
        }
    }
#pragma unroll
    for (int i = 0; i < 16; i++)
        g_M[(size_t)b * CD * CD + (og * 16 + i) * CD + ct * 32 + cl] = a[i];
}

// ---------------------------------------------------------------------------
// kernel_launch: launches only. No attributes (all static smem <= 48KB).
// ---------------------------------------------------------------------------
extern "C" void kernel_launch(void* const* d_in, const int* in_sizes, int n_in,
                              void* d_out, int out_size)
{
    const float* x     = (const float*)d_in[0];
    const float* w_qkv = (const float*)d_in[1];
    const float* w_out = (const float*)d_in[2];
    const float* b_out = (const float*)d_in[3];
    float* y = (float*)d_out;

    gemm_tc<0><<<dim3(128, BATCH), 256>>>(w_qkv + 128 * CD, x, nullptr, nullptr);
    gemm_tc<1><<<dim3(NCH, BATCH), 256>>>(nullptr, x, nullptr, nullptr);
    reduce_scale<<<1024, 128>>>();
    ctx_kernel<<<dim3(BATCH, 4), 1024>>>(w_qkv);
    u_kernel<<<BATCH, 1024>>>(w_out);
    m_kernel<<<dim3(BATCH, 4), 256>>>(w_qkv);
    gemm_tc<2><<<dim3(128, BATCH), 256>>>(nullptr, x, b_out, y);
}